// round 1
// baseline (speedup 1.0000x reference)
#include <cuda_runtime.h>
#include <math.h>

// ---------------- problem constants ----------------
#define BATCH   2
#define SEQL    2048
#define DM      1024
#define DIN     2048      // D_INNER
#define DSTATE  128
#define NH      32
#define HD      64
#define DPROJ   4384      // D_IN_PROJ
#define CONVCH  2304      // D_INNER + 2*D_STATE
#define NCHUNK  16
#define CH      128
#define EPSV    1e-5f
#define ROWS    (BATCH*SEQL)   // 4096

// ---------------- scratch (device globals: no allocation allowed) ----------------
__device__ float g_xn    [ROWS*DM];                       // rmsnorm(x)
__device__ float g_zx    [ROWS*DPROJ];                    // in-proj output (per dir, reused)
__device__ float g_xBC   [ROWS*CONVCH];                   // conv+silu output
__device__ float g_dt    [ROWS*NH];                       // softplus dt
__device__ float g_Acs   [BATCH*NH*SEQL];                 // per-chunk inclusive cumsum of A*dt
__device__ float g_states[BATCH*NCHUNK*NH*HD*DSTATE];     // chunk states
__device__ float g_prev  [BATCH*NCHUNK*NH*HD*DSTATE];     // pre-chunk states (scan out)
__device__ float g_S     [BATCH*NCHUNK*CH*CH];            // C @ B^T per (b,c)
__device__ float g_y     [ROWS*DIN];                      // SSD output / gated-norm output
__device__ float g_ycat  [ROWS*2*DM];                     // [y_fwd | y_bwd]

// ---------------- K1: rmsnorm over d_model ----------------
__global__ void k_rmsnorm(const float* __restrict__ x, const float* __restrict__ w) {
    int row = blockIdx.x;
    const float* xr = x + (size_t)row * DM;
    float ss = 0.f;
    for (int i = threadIdx.x; i < DM; i += 256) { float v = xr[i]; ss += v * v; }
    __shared__ float sred[8];
    for (int o = 16; o > 0; o >>= 1) ss += __shfl_xor_sync(0xffffffffu, ss, o);
    if ((threadIdx.x & 31) == 0) sred[threadIdx.x >> 5] = ss;
    __syncthreads();
    if (threadIdx.x == 0) {
        float t = 0.f;
        for (int i = 0; i < 8; i++) t += sred[i];
        sred[0] = t;
    }
    __syncthreads();
    float scale = rsqrtf(sred[0] / (float)DM + EPSV);
    for (int i = threadIdx.x; i < DM; i += 256)
        g_xn[(size_t)row * DM + i] = xr[i] * scale * w[i];
}

// ---------------- shared SGEMM: C[M,N] = A[M,K] @ W[N,K]^T (+bias +resid) ----------------
// 128x128 tile, BK=8, 256 threads, 8x8 microtile. flipA/flipC flip the seq index
// within each batch (row r = b*SEQL + l  ->  b*SEQL + (SEQL-1-l)).
__global__ void __launch_bounds__(256) k_sgemm(
    const float* __restrict__ A, int lda, int flipA,
    const float* __restrict__ W, int K,
    float* __restrict__ C, int ldc, int flipC,
    int M, int N,
    const float* __restrict__ resid, const float* __restrict__ bias)
{
    __shared__ float sA[8][132];
    __shared__ float sB[8][132];
    const int bm = blockIdx.y * 128, bn = blockIdx.x * 128;
    const int tid = threadIdx.x;
    const int tx = tid & 15, ty = tid >> 4;
    float acc[8][8];
#pragma unroll
    for (int i = 0; i < 8; i++)
#pragma unroll
        for (int j = 0; j < 8; j++) acc[i][j] = 0.f;

    for (int k0 = 0; k0 < K; k0 += 8) {
#pragma unroll
        for (int i = 0; i < 4; i++) {
            int idx = tid + i * 256;        // 0..1023
            int r = idx >> 3, c = idx & 7;
            int gr = bm + r;
            float va = 0.f;
            if (gr < M) {
                int pr = gr;
                if (flipA) { int b = gr / SEQL, l = gr % SEQL; pr = b * SEQL + (SEQL - 1 - l); }
                va = A[(size_t)pr * lda + k0 + c];
            }
            sA[c][r] = va;
            int gn = bn + r;
            float vw = 0.f;
            if (gn < N) vw = W[(size_t)gn * K + k0 + c];
            sB[c][r] = vw;
        }
        __syncthreads();
#pragma unroll
        for (int kk = 0; kk < 8; kk++) {
            float a[8], bv[8];
#pragma unroll
            for (int i = 0; i < 8; i++) a[i] = sA[kk][ty * 8 + i];
#pragma unroll
            for (int j = 0; j < 8; j++) bv[j] = sB[kk][tx * 8 + j];
#pragma unroll
            for (int i = 0; i < 8; i++)
#pragma unroll
                for (int j = 0; j < 8; j++) acc[i][j] += a[i] * bv[j];
        }
        __syncthreads();
    }
#pragma unroll
    for (int i = 0; i < 8; i++) {
        int gr = bm + ty * 8 + i;
        if (gr >= M) continue;
        int pr = gr;
        if (flipC) { int b = gr / SEQL, l = gr % SEQL; pr = b * SEQL + (SEQL - 1 - l); }
#pragma unroll
        for (int j = 0; j < 8; j++) {
            int gn = bn + tx * 8 + j;
            if (gn >= N) continue;
            float v = acc[i][j];
            if (bias)  v += bias[gn];
            if (resid) v += resid[(size_t)pr * N + gn];
            C[(size_t)pr * ldc + gn] = v;
        }
    }
}

// ---------------- K3: dt = softplus(zx[..., 4352+h] + dt_bias) ----------------
__global__ void k_dt(const float* __restrict__ dt_bias) {
    int idx = blockIdx.x * 256 + threadIdx.x;
    if (idx >= ROWS * NH) return;
    int h = idx % NH, r = idx / NH;
    float v = g_zx[(size_t)r * DPROJ + DIN + CONVCH + h] + dt_bias[h];
    g_dt[idx] = (v > 20.f) ? v : log1pf(expf(v));
}

// ---------------- K4: causal depthwise conv (k=4) + bias + silu ----------------
__global__ void k_conv(const float* __restrict__ conv_w, const float* __restrict__ conv_b) {
    int idx = blockIdx.x * 256 + threadIdx.x;
    if (idx >= ROWS * CONVCH) return;
    int ch = idx % CONVCH;
    int r = idx / CONVCH;
    int b = r / SEQL, l = r % SEQL;
    float acc = conv_b[ch];
#pragma unroll
    for (int k = 0; k < 4; k++) {
        int ll = l - 3 + k;
        if (ll >= 0)
            acc += g_zx[(size_t)(b * SEQL + ll) * DPROJ + DIN + ch] * conv_w[ch * 4 + k];
    }
    g_xBC[idx] = acc / (1.f + expf(-acc));   // silu
}

// ---------------- K5: per-chunk inclusive cumsum of A*dt ----------------
__global__ void k_acs(const float* __restrict__ A_log) {
    int c = blockIdx.x % NCHUNK;
    int h = (blockIdx.x / NCHUNK) % NH;
    int b = blockIdx.x / (NCHUNK * NH);
    int l = threadIdx.x;    // 0..127
    float Aneg = -expf(A_log[h]);
    int row = b * SEQL + c * CH + l;
    float x = Aneg * g_dt[row * NH + h];
    __shared__ float wsum[4];
    for (int o = 1; o < 32; o <<= 1) {
        float t = __shfl_up_sync(0xffffffffu, x, o);
        if ((l & 31) >= o) x += t;
    }
    if ((l & 31) == 31) wsum[l >> 5] = x;
    __syncthreads();
    float add = 0.f;
    int w = l >> 5;
    for (int i = 0; i < w; i++) add += wsum[i];
    g_Acs[(b * NH + h) * SEQL + c * CH + l] = x + add;
}

// ---------------- K6: states[b,c,h,p,n] = sum_l X*dt*decay * B ----------------
__global__ void __launch_bounds__(256) k_states() {
    int h = blockIdx.x % NH;
    int c = (blockIdx.x / NH) % NCHUNK;
    int b = blockIdx.x / (NH * NCHUNK);
    __shared__ float sX[32][64];
    __shared__ float sB[32][132];
    int tid = threadIdx.x;
    int tx = tid & 15, ty = tid >> 4;   // tx -> n block (8 wide), ty -> p block (4 wide)
    float acc[4][8];
#pragma unroll
    for (int i = 0; i < 4; i++)
#pragma unroll
        for (int j = 0; j < 8; j++) acc[i][j] = 0.f;

    const float* AcsRow = g_Acs + (b * NH + h) * SEQL + c * CH;
    float AcsLast = AcsRow[127];

    for (int lt = 0; lt < 4; lt++) {
        for (int i = tid; i < 32 * 64; i += 256) {
            int l = i >> 6, p = i & 63;
            int row = b * SEQL + c * CH + lt * 32 + l;
            float w = g_dt[row * NH + h] * expf(AcsLast - AcsRow[lt * 32 + l]);
            sX[l][p] = g_xBC[(size_t)row * CONVCH + h * HD + p] * w;
        }
        for (int i = tid; i < 32 * 128; i += 256) {
            int l = i >> 7, n = i & 127;
            int row = b * SEQL + c * CH + lt * 32 + l;
            sB[l][n] = g_xBC[(size_t)row * CONVCH + DIN + n];
        }
        __syncthreads();
#pragma unroll
        for (int l = 0; l < 32; l++) {
            float xv[4], bv[8];
#pragma unroll
            for (int i = 0; i < 4; i++) xv[i] = sX[l][ty * 4 + i];
#pragma unroll
            for (int j = 0; j < 8; j++) bv[j] = sB[l][tx * 8 + j];
#pragma unroll
            for (int i = 0; i < 4; i++)
#pragma unroll
                for (int j = 0; j < 8; j++) acc[i][j] += xv[i] * bv[j];
        }
        __syncthreads();
    }
    size_t base = ((size_t)(b * NCHUNK + c) * NH + h) * HD * DSTATE;
#pragma unroll
    for (int i = 0; i < 4; i++)
#pragma unroll
        for (int j = 0; j < 8; j++)
            g_states[base + (ty * 4 + i) * DSTATE + tx * 8 + j] = acc[i][j];
}

// ---------------- K7: sequential chunk scan over c (16 steps) ----------------
__global__ void k_scan() {
    int h = blockIdx.x % NH, b = blockIdx.x / NH;
    int tid = threadIdx.x;
    float s[32];
#pragma unroll
    for (int k = 0; k < 32; k++) s[k] = 0.f;
    for (int c = 0; c < NCHUNK; c++) {
        float cd = expf(g_Acs[(b * NH + h) * SEQL + c * CH + 127]);
        size_t base = ((size_t)(b * NCHUNK + c) * NH + h) * HD * DSTATE;
#pragma unroll
        for (int k = 0; k < 32; k++) {
            int e = k * 256 + tid;
            g_prev[base + e] = s[k];
            s[k] = s[k] * cd + g_states[base + e];
        }
    }
}

// ---------------- K8: S[b,c,l,s] = C_c @ B_c^T (shared across heads) ----------------
__global__ void __launch_bounds__(256) k_cb() {
    int c = blockIdx.x % NCHUNK, b = blockIdx.x / NCHUNK;
    __shared__ float sC[32][132];
    __shared__ float sBm[32][132];
    int tid = threadIdx.x, tx = tid & 15, ty = tid >> 4;
    float acc[8][8];
#pragma unroll
    for (int i = 0; i < 8; i++)
#pragma unroll
        for (int j = 0; j < 8; j++) acc[i][j] = 0.f;

    for (int k0 = 0; k0 < DSTATE; k0 += 32) {
        for (int i = tid; i < 32 * 128; i += 256) {
            int kk = i & 31, l = i >> 5;
            int row = b * SEQL + c * CH + l;
            sC[kk][l]  = g_xBC[(size_t)row * CONVCH + DIN + DSTATE + k0 + kk];
            sBm[kk][l] = g_xBC[(size_t)row * CONVCH + DIN + k0 + kk];
        }
        __syncthreads();
#pragma unroll
        for (int kk = 0; kk < 32; kk++) {
            float a[8], bv[8];
#pragma unroll
            for (int i = 0; i < 8; i++) a[i] = sC[kk][ty * 8 + i];
#pragma unroll
            for (int j = 0; j < 8; j++) bv[j] = sBm[kk][tx * 8 + j];
#pragma unroll
            for (int i = 0; i < 8; i++)
#pragma unroll
                for (int j = 0; j < 8; j++) acc[i][j] += a[i] * bv[j];
        }
        __syncthreads();
    }
    size_t base = (size_t)(b * NCHUNK + c) * CH * CH;
#pragma unroll
    for (int i = 0; i < 8; i++)
#pragma unroll
        for (int j = 0; j < 8; j++)
            g_S[base + (ty * 8 + i) * CH + tx * 8 + j] = acc[i][j];
}

// ---------------- K9: Y = Y_diag + Y_off + xs*D  per (b,c,h) ----------------
__global__ void __launch_bounds__(256) k_y(const float* __restrict__ Dvec) {
    int h = blockIdx.x % NH;
    int c = (blockIdx.x / NH) % NCHUNK;
    int b = blockIdx.x / (NH * NCHUNK);
    __shared__ float sG[128][33];
    __shared__ float sT[32][69];
    __shared__ float sAcs[128];
    int tid = threadIdx.x;
    int pb = tid & 15;    // p base = pb*4
    int lb = tid >> 4;    // l base = lb*8
    if (tid < 128) sAcs[tid] = g_Acs[(b * NH + h) * SEQL + c * CH + tid];
    __syncthreads();

    float acc[8][4], acc2[8][4];
#pragma unroll
    for (int i = 0; i < 8; i++)
#pragma unroll
        for (int j = 0; j < 4; j++) { acc[i][j] = 0.f; acc2[i][j] = 0.f; }

    size_t Sbase = (size_t)(b * NCHUNK + c) * CH * CH;
    // ---- phase A: Y_diag = (CB^T * L) @ (xs*dt) ----
    for (int st = 0; st < 4; st++) {
        for (int i = tid; i < 128 * 32; i += 256) {
            int s = i & 31, l = i >> 5;
            int sg = st * 32 + s;
            float v = 0.f;
            if (sg <= l) v = g_S[Sbase + l * CH + sg] * expf(sAcs[l] - sAcs[sg]);
            sG[l][s] = v;
        }
        for (int i = tid; i < 32 * 64; i += 256) {
            int p = i & 63, s = i >> 6;
            int row = b * SEQL + c * CH + st * 32 + s;
            sT[s][p] = g_xBC[(size_t)row * CONVCH + h * HD + p] * g_dt[row * NH + h];
        }
        __syncthreads();
#pragma unroll
        for (int s = 0; s < 32; s++) {
            float gv[8], xv[4];
#pragma unroll
            for (int i = 0; i < 8; i++) gv[i] = sG[lb * 8 + i][s];
#pragma unroll
            for (int j = 0; j < 4; j++) xv[j] = sT[s][pb * 4 + j];
#pragma unroll
            for (int i = 0; i < 8; i++)
#pragma unroll
                for (int j = 0; j < 4; j++) acc[i][j] += gv[i] * xv[j];
        }
        __syncthreads();
    }
    // ---- phase B: Y_off = exp(Acs[l]) * C @ prev^T ----
    size_t Pbase = ((size_t)(b * NCHUNK + c) * NH + h) * HD * DSTATE;
    for (int nt = 0; nt < 4; nt++) {
        for (int i = tid; i < 128 * 32; i += 256) {
            int n = i & 31, l = i >> 5;
            int row = b * SEQL + c * CH + l;
            sG[l][n] = g_xBC[(size_t)row * CONVCH + DIN + DSTATE + nt * 32 + n];
        }
        for (int i = tid; i < 32 * 64; i += 256) {
            int n = i & 31, p = i >> 5;
            sT[n][p] = g_prev[Pbase + p * DSTATE + nt * 32 + n];
        }
        __syncthreads();
#pragma unroll
        for (int n = 0; n < 32; n++) {
            float gv[8], pv[4];
#pragma unroll
            for (int i = 0; i < 8; i++) gv[i] = sG[lb * 8 + i][n];
#pragma unroll
            for (int j = 0; j < 4; j++) pv[j] = sT[n][pb * 4 + j];
#pragma unroll
            for (int i = 0; i < 8; i++)
#pragma unroll
                for (int j = 0; j < 4; j++) acc2[i][j] += gv[i] * pv[j];
        }
        __syncthreads();
    }
    // ---- combine + skip ----
    float Dh = Dvec[h];
#pragma unroll
    for (int i = 0; i < 8; i++) {
        int l = lb * 8 + i;
        int row = b * SEQL + c * CH + l;
        float el = expf(sAcs[l]);
#pragma unroll
        for (int j = 0; j < 4; j++) {
            int p = pb * 4 + j;
            float xsv = g_xBC[(size_t)row * CONVCH + h * HD + p];
            g_y[(size_t)row * DIN + h * HD + p] = acc[i][j] + el * acc2[i][j] + xsv * Dh;
        }
    }
}

// ---------------- K10: gated rmsnorm: y = rmsnorm(y * silu(z)) * w ----------------
__global__ void k_gnorm(const float* __restrict__ gnorm_w) {
    int row = blockIdx.x;
    __shared__ float st[DIN];
    __shared__ float sred[8];
    float ss = 0.f;
    for (int i = threadIdx.x; i < DIN; i += 256) {
        float z = g_zx[(size_t)row * DPROJ + i];
        float t = g_y[(size_t)row * DIN + i] * (z / (1.f + expf(-z)));
        st[i] = t;
        ss += t * t;
    }
    for (int o = 16; o > 0; o >>= 1) ss += __shfl_xor_sync(0xffffffffu, ss, o);
    if ((threadIdx.x & 31) == 0) sred[threadIdx.x >> 5] = ss;
    __syncthreads();
    if (threadIdx.x == 0) {
        float t = 0.f;
        for (int i = 0; i < 8; i++) t += sred[i];
        sred[0] = t;
    }
    __syncthreads();
    float scale = rsqrtf(sred[0] / (float)DIN + EPSV);
    for (int i = threadIdx.x; i < DIN; i += 256)
        g_y[(size_t)row * DIN + i] = st[i] * scale * gnorm_w[i];
}

// ---------------- launch ----------------
extern "C" void kernel_launch(void* const* d_in, const int* in_sizes, int n_in,
                              void* d_out, int out_size) {
    (void)in_sizes; (void)n_in; (void)out_size;
    const float* x         = (const float*)d_in[0];
    const float* norm_w    = (const float*)d_in[1];
    const float* out_w_blk = (const float*)d_in[2];
    const float* out_b_blk = (const float*)d_in[3];

    float *p_xn, *p_zx, *p_y, *p_ycat;
    cudaGetSymbolAddress((void**)&p_xn,   g_xn);
    cudaGetSymbolAddress((void**)&p_zx,   g_zx);
    cudaGetSymbolAddress((void**)&p_y,    g_y);
    cudaGetSymbolAddress((void**)&p_ycat, g_ycat);

    k_rmsnorm<<<ROWS, 256>>>(x, norm_w);

    for (int d = 0; d < 2; d++) {
        const float* in_w    = (const float*)d_in[4 + d * 8 + 0];
        const float* conv_w  = (const float*)d_in[4 + d * 8 + 1];
        const float* conv_b  = (const float*)d_in[4 + d * 8 + 2];
        const float* dt_bias = (const float*)d_in[4 + d * 8 + 3];
        const float* A_log   = (const float*)d_in[4 + d * 8 + 4];
        const float* Dv      = (const float*)d_in[4 + d * 8 + 5];
        const float* gnw     = (const float*)d_in[4 + d * 8 + 6];
        const float* out_w   = (const float*)d_in[4 + d * 8 + 7];

        dim3 g2((DPROJ + 127) / 128, ROWS / 128);
        k_sgemm<<<g2, 256>>>(p_xn, DM, d, in_w, DM, p_zx, DPROJ, 0, ROWS, DPROJ,
                             nullptr, nullptr);
        k_dt<<<(ROWS * NH + 255) / 256, 256>>>(dt_bias);
        k_conv<<<(ROWS * CONVCH + 255) / 256, 256>>>(conv_w, conv_b);
        k_acs<<<BATCH * NH * NCHUNK, 128>>>(A_log);
        k_states<<<BATCH * NCHUNK * NH, 256>>>();
        k_scan<<<BATCH * NH, 256>>>();
        k_cb<<<BATCH * NCHUNK, 256>>>();
        k_y<<<BATCH * NCHUNK * NH, 256>>>(Dv);
        k_gnorm<<<ROWS, 256>>>(gnw);

        dim3 g9(DM / 128, ROWS / 128);
        k_sgemm<<<g9, 256>>>(p_y, DIN, 0, out_w, DIN, p_ycat + d * DM, 2 * DM, d,
                             ROWS, DM, nullptr, nullptr);
    }

    dim3 gf(DM / 128, ROWS / 128);
    k_sgemm<<<gf, 256>>>(p_ycat, 2 * DM, 0, out_w_blk, 2 * DM, (float*)d_out, DM, 0,
                         ROWS, DM, x, out_b_blk);
}

// round 3
// speedup vs baseline: 3.2629x; 3.2629x over previous
#include <cuda_runtime.h>
#include <cuda_bf16.h>
#include <math.h>
#include <stdint.h>

// ---------------- problem constants ----------------
#define BATCH   2
#define SEQL    2048
#define DM      1024
#define DIN     2048      // D_INNER
#define DSTATE  128
#define NH      32
#define HD      64
#define DPROJ   4384      // D_IN_PROJ
#define CONVCH  2304      // D_INNER + 2*D_STATE
#define NCHUNK  16
#define CH      128
#define EPSV    1e-5f
#define ROWS    (BATCH*SEQL)   // 4096
#define NPADW   4480           // 35*128, padded N for widest weight

// ---------------- scratch (device globals: no allocation allowed) ----------------
__device__ float g_xn    [ROWS*DM];
__device__ float g_zx    [ROWS*DPROJ];
__device__ float g_xBC   [ROWS*CONVCH];
__device__ float g_dt    [ROWS*NH];
__device__ float g_Acs   [BATCH*NH*SEQL];
__device__ float g_states[BATCH*NCHUNK*NH*HD*DSTATE];
__device__ float g_prev  [BATCH*NCHUNK*NH*HD*DSTATE];
__device__ float g_S     [BATCH*NCHUNK*CH*CH];
__device__ float g_y     [ROWS*DIN];
__device__ float g_ycat  [ROWS*2*DM];

// bf16 hi/lo staging for tensor-core GEMMs
__device__ __nv_bfloat16 g_XNhi[ROWS*DM];
__device__ __nv_bfloat16 g_XNlo[ROWS*DM];
__device__ __nv_bfloat16 g_Ahi [ROWS*DIN];
__device__ __nv_bfloat16 g_Alo [ROWS*DIN];
__device__ __nv_bfloat16 g_Whi [NPADW*DM];   // 4.59M elems, also fits 1024x2048
__device__ __nv_bfloat16 g_Wlo [NPADW*DM];

// ---------------- asm helpers ----------------
__device__ __forceinline__ uint32_t smem_u32(const void* p) {
    uint32_t a;
    asm("{ .reg .u64 t; cvta.to.shared.u64 t, %1; cvt.u32.u64 %0, t; }" : "=r"(a) : "l"(p));
    return a;
}
#define CP16(d, s) asm volatile("cp.async.cg.shared.global [%0], [%1], 16;" :: "r"(d), "l"(s))
#define CP_COMMIT() asm volatile("cp.async.commit_group;")
#define LDSM4(r, a) asm volatile("ldmatrix.sync.aligned.m8n8.x4.shared.b16 {%0,%1,%2,%3}, [%4];" \
    : "=r"((r)[0]), "=r"((r)[1]), "=r"((r)[2]), "=r"((r)[3]) : "r"(a))
#define MMA16816(d, a, b) asm volatile( \
    "mma.sync.aligned.m16n8k16.row.col.f32.bf16.bf16.f32 " \
    "{%0,%1,%2,%3}, {%4,%5,%6,%7}, {%8,%9}, {%0,%1,%2,%3};" \
    : "+f"((d)[0]), "+f"((d)[1]), "+f"((d)[2]), "+f"((d)[3]) \
    : "r"((a)[0]), "r"((a)[1]), "r"((a)[2]), "r"((a)[3]), "r"((b)[0]), "r"((b)[1]))

// swizzled smem address: rows of 64B (32 bf16), 16B chunks XOR'd for
// conflict-free ldmatrix column gathers (chunk ^= (row>>1)&3).
__device__ __forceinline__ uint32_t sw_addr(uint32_t base, int row, int chunk) {
    return base + (uint32_t)row * 64u + ((((uint32_t)chunk) ^ (((uint32_t)row >> 1) & 3u)) << 4);
}

// ---------------- fp32 -> bf16 hi/lo conversion (with zero padding) ----------------
__global__ void k_cvt(const float* __restrict__ src, __nv_bfloat16* __restrict__ hi,
                      __nv_bfloat16* __restrict__ lo, long nvalid, long total) {
    long idx = ((long)blockIdx.x * 256 + threadIdx.x) * 8;
    if (idx >= total) return;
    uint4 hq = make_uint4(0, 0, 0, 0), lq = make_uint4(0, 0, 0, 0);
    if (idx < nvalid) {
        float4 f0 = *reinterpret_cast<const float4*>(src + idx);
        float4 f1 = *reinterpret_cast<const float4*>(src + idx + 4);
        float f[8] = {f0.x, f0.y, f0.z, f0.w, f1.x, f1.y, f1.z, f1.w};
        uint32_t h[8], l[8];
#pragma unroll
        for (int i = 0; i < 8; i++) {
            __nv_bfloat16 hb = __float2bfloat16(f[i]);
            float rr = f[i] - __bfloat162float(hb);
            __nv_bfloat16 lb = __float2bfloat16(rr);
            h[i] = __bfloat16_as_ushort(hb);
            l[i] = __bfloat16_as_ushort(lb);
        }
        hq.x = (h[1] << 16) | h[0]; hq.y = (h[3] << 16) | h[2];
        hq.z = (h[5] << 16) | h[4]; hq.w = (h[7] << 16) | h[6];
        lq.x = (l[1] << 16) | l[0]; lq.y = (l[3] << 16) | l[2];
        lq.z = (l[5] << 16) | l[4]; lq.w = (l[7] << 16) | l[6];
    }
    *reinterpret_cast<uint4*>(hi + idx) = hq;
    *reinterpret_cast<uint4*>(lo + idx) = lq;
}

// ---------------- HMMA GEMM: C[4096,N] = A[4096,K] @ W[N,K]^T (+bias +resid) ----------------
// 128x128x32 tile, 256 threads, bf16 hi/lo 3-term split, cp.async double buffer.
#define HSMEM 65536   // 2 stages x (Ahi 8K + Alo 8K + Bhi 8K + Blo 8K)

__global__ void __launch_bounds__(256, 1) k_hgemm(
    const __nv_bfloat16* __restrict__ Ahi, const __nv_bfloat16* __restrict__ Alo,
    int K, int flipA,
    const __nv_bfloat16* __restrict__ Whi, const __nv_bfloat16* __restrict__ Wlo,
    int Ntot, float* __restrict__ C, int ldc, int flipC,
    const float* __restrict__ resid, const float* __restrict__ bias)
{
    extern __shared__ char smraw[];
    const uint32_t sb = smem_u32(smraw);
    const int tid = threadIdx.x, lane = tid & 31, wid = tid >> 5;
    const int bm = blockIdx.y * 128, bn = blockIdx.x * 128;
    const int wm = (wid & 1) * 64, wn = (wid >> 1) * 32;

    float acc[4][4][4];
#pragma unroll
    for (int i = 0; i < 4; i++)
#pragma unroll
        for (int j = 0; j < 4; j++)
#pragma unroll
            for (int k = 0; k < 4; k++) acc[i][j][k] = 0.f;

    const int ktiles = K / 32;

    auto load_stage = [&](int s, int k0) {
        uint32_t base = sb + s * 32768;
#pragma unroll
        for (int it = 0; it < 2; it++) {
            int q = tid + it * 256;              // 0..511
            int r = q >> 2, c = q & 3;
            int gr = bm + r, pr = gr;
            if (flipA) pr = (gr & ~(SEQL - 1)) + (SEQL - 1 - (gr & (SEQL - 1)));
            uint32_t d = sw_addr(base, r, c);
            size_t aoff = (size_t)pr * K + k0 + c * 8;
            CP16(d,         (const char*)(Ahi + aoff));
            CP16(d + 8192,  (const char*)(Alo + aoff));
            size_t woff = (size_t)(bn + r) * K + k0 + c * 8;
            CP16(d + 16384, (const char*)(Whi + woff));
            CP16(d + 24576, (const char*)(Wlo + woff));
        }
        CP_COMMIT();
    };

    load_stage(0, 0);

    for (int i = 0; i < ktiles; i++) {
        if (i + 1 < ktiles) {
            load_stage((i + 1) & 1, (i + 1) * 32);
            asm volatile("cp.async.wait_group 1;");
        } else {
            asm volatile("cp.async.wait_group 0;");
        }
        __syncthreads();
        uint32_t base = sb + (i & 1) * 32768;
#pragma unroll
        for (int ks = 0; ks < 2; ks++) {
            const int kb = ks * 2;
            uint32_t ah[4][4], al[4][4], bh[4][2], bl[4][2];
            // A hi fragments (4 x m16k16)
#pragma unroll
            for (int mf = 0; mf < 4; mf++) {
                int rr = wm + mf * 16 + (lane & 15);
                int cc = kb + (lane >> 4);
                LDSM4(ah[mf], sw_addr(base, rr, cc));
            }
            // B hi / lo fragments (4 x n8k16, two per ldmatrix.x4)
#pragma unroll
            for (int p2 = 0; p2 < 2; p2++) {
                int rr = wn + p2 * 16 + ((lane >> 4) << 3) + (lane & 7);
                int cc = kb + ((lane >> 3) & 1);
                uint32_t bd = sw_addr(base + 16384, rr, cc);
                uint32_t t[4];
                LDSM4(t, bd);
                bh[p2 * 2][0] = t[0]; bh[p2 * 2][1] = t[1];
                bh[p2 * 2 + 1][0] = t[2]; bh[p2 * 2 + 1][1] = t[3];
                LDSM4(t, bd + 8192);
                bl[p2 * 2][0] = t[0]; bl[p2 * 2][1] = t[1];
                bl[p2 * 2 + 1][0] = t[2]; bl[p2 * 2 + 1][1] = t[3];
            }
#pragma unroll
            for (int mf = 0; mf < 4; mf++)
#pragma unroll
                for (int nf = 0; nf < 4; nf++) MMA16816(acc[mf][nf], ah[mf], bh[nf]);
#pragma unroll
            for (int mf = 0; mf < 4; mf++)
#pragma unroll
                for (int nf = 0; nf < 4; nf++) MMA16816(acc[mf][nf], ah[mf], bl[nf]);
            // A lo fragments
#pragma unroll
            for (int mf = 0; mf < 4; mf++) {
                int rr = wm + mf * 16 + (lane & 15);
                int cc = kb + (lane >> 4);
                LDSM4(al[mf], sw_addr(base + 8192, rr, cc));
            }
#pragma unroll
            for (int mf = 0; mf < 4; mf++)
#pragma unroll
                for (int nf = 0; nf < 4; nf++) MMA16816(acc[mf][nf], al[mf], bh[nf]);
        }
        __syncthreads();
    }

    // epilogue
#pragma unroll
    for (int mf = 0; mf < 4; mf++) {
        int r0 = bm + wm + mf * 16 + (lane >> 2);
        int r1 = r0 + 8;
        int p0 = r0, p1 = r1;
        if (flipC) {
            p0 = (r0 & ~(SEQL - 1)) + (SEQL - 1 - (r0 & (SEQL - 1)));
            p1 = (r1 & ~(SEQL - 1)) + (SEQL - 1 - (r1 & (SEQL - 1)));
        }
#pragma unroll
        for (int nf = 0; nf < 4; nf++) {
            int col = bn + wn + nf * 8 + (lane & 3) * 2;
            if (col >= Ntot) continue;
            float2 v0 = make_float2(acc[mf][nf][0], acc[mf][nf][1]);
            float2 v1 = make_float2(acc[mf][nf][2], acc[mf][nf][3]);
            if (bias) {
                float b0 = bias[col], b1 = bias[col + 1];
                v0.x += b0; v0.y += b1; v1.x += b0; v1.y += b1;
            }
            if (resid) {
                float2 q0 = *reinterpret_cast<const float2*>(resid + (size_t)p0 * ldc + col);
                float2 q1 = *reinterpret_cast<const float2*>(resid + (size_t)p1 * ldc + col);
                v0.x += q0.x; v0.y += q0.y; v1.x += q1.x; v1.y += q1.y;
            }
            *reinterpret_cast<float2*>(C + (size_t)p0 * ldc + col) = v0;
            *reinterpret_cast<float2*>(C + (size_t)p1 * ldc + col) = v1;
        }
    }
}

// ---------------- K1: rmsnorm over d_model ----------------
__global__ void k_rmsnorm(const float* __restrict__ x, const float* __restrict__ w) {
    int row = blockIdx.x;
    const float* xr = x + (size_t)row * DM;
    float ss = 0.f;
    for (int i = threadIdx.x; i < DM; i += 256) { float v = xr[i]; ss += v * v; }
    __shared__ float sred[8];
    for (int o = 16; o > 0; o >>= 1) ss += __shfl_xor_sync(0xffffffffu, ss, o);
    if ((threadIdx.x & 31) == 0) sred[threadIdx.x >> 5] = ss;
    __syncthreads();
    if (threadIdx.x == 0) {
        float t = 0.f;
        for (int i = 0; i < 8; i++) t += sred[i];
        sred[0] = t;
    }
    __syncthreads();
    float scale = rsqrtf(sred[0] / (float)DM + EPSV);
    for (int i = threadIdx.x; i < DM; i += 256)
        g_xn[(size_t)row * DM + i] = xr[i] * scale * w[i];
}

// ---------------- K3: dt = softplus ----------------
__global__ void k_dt(const float* __restrict__ dt_bias) {
    int idx = blockIdx.x * 256 + threadIdx.x;
    if (idx >= ROWS * NH) return;
    int h = idx % NH, r = idx / NH;
    float v = g_zx[(size_t)r * DPROJ + DIN + CONVCH + h] + dt_bias[h];
    g_dt[idx] = (v > 20.f) ? v : log1pf(expf(v));
}

// ---------------- K4: causal depthwise conv (k=4) + bias + silu ----------------
__global__ void k_conv(const float* __restrict__ conv_w, const float* __restrict__ conv_b) {
    int idx = blockIdx.x * 256 + threadIdx.x;
    if (idx >= ROWS * CONVCH) return;
    int ch = idx % CONVCH;
    int r = idx / CONVCH;
    int b = r / SEQL, l = r % SEQL;
    float acc = conv_b[ch];
#pragma unroll
    for (int k = 0; k < 4; k++) {
        int ll = l - 3 + k;
        if (ll >= 0)
            acc += g_zx[(size_t)(b * SEQL + ll) * DPROJ + DIN + ch] * conv_w[ch * 4 + k];
    }
    g_xBC[idx] = acc / (1.f + expf(-acc));
}

// ---------------- K5: per-chunk inclusive cumsum of A*dt ----------------
__global__ void k_acs(const float* __restrict__ A_log) {
    int c = blockIdx.x % NCHUNK;
    int h = (blockIdx.x / NCHUNK) % NH;
    int b = blockIdx.x / (NCHUNK * NH);
    int l = threadIdx.x;
    float Aneg = -expf(A_log[h]);
    int row = b * SEQL + c * CH + l;
    float x = Aneg * g_dt[row * NH + h];
    __shared__ float wsum[4];
    for (int o = 1; o < 32; o <<= 1) {
        float t = __shfl_up_sync(0xffffffffu, x, o);
        if ((l & 31) >= o) x += t;
    }
    if ((l & 31) == 31) wsum[l >> 5] = x;
    __syncthreads();
    float add = 0.f;
    int w = l >> 5;
    for (int i = 0; i < w; i++) add += wsum[i];
    g_Acs[(b * NH + h) * SEQL + c * CH + l] = x + add;
}

// ---------------- K6: chunk states ----------------
__global__ void __launch_bounds__(256) k_states() {
    int h = blockIdx.x % NH;
    int c = (blockIdx.x / NH) % NCHUNK;
    int b = blockIdx.x / (NH * NCHUNK);
    __shared__ float sX[32][64];
    __shared__ float sB[32][132];
    int tid = threadIdx.x;
    int tx = tid & 15, ty = tid >> 4;
    float acc[4][8];
#pragma unroll
    for (int i = 0; i < 4; i++)
#pragma unroll
        for (int j = 0; j < 8; j++) acc[i][j] = 0.f;

    const float* AcsRow = g_Acs + (b * NH + h) * SEQL + c * CH;
    float AcsLast = AcsRow[127];

    for (int lt = 0; lt < 4; lt++) {
        for (int i = tid; i < 32 * 64; i += 256) {
            int l = i >> 6, p = i & 63;
            int row = b * SEQL + c * CH + lt * 32 + l;
            float w = g_dt[row * NH + h] * expf(AcsLast - AcsRow[lt * 32 + l]);
            sX[l][p] = g_xBC[(size_t)row * CONVCH + h * HD + p] * w;
        }
        for (int i = tid; i < 32 * 128; i += 256) {
            int l = i >> 7, n = i & 127;
            int row = b * SEQL + c * CH + lt * 32 + l;
            sB[l][n] = g_xBC[(size_t)row * CONVCH + DIN + n];
        }
        __syncthreads();
#pragma unroll
        for (int l = 0; l < 32; l++) {
            float xv[4], bv[8];
#pragma unroll
            for (int i = 0; i < 4; i++) xv[i] = sX[l][ty * 4 + i];
#pragma unroll
            for (int j = 0; j < 8; j++) bv[j] = sB[l][tx * 8 + j];
#pragma unroll
            for (int i = 0; i < 4; i++)
#pragma unroll
                for (int j = 0; j < 8; j++) acc[i][j] += xv[i] * bv[j];
        }
        __syncthreads();
    }
    size_t base = ((size_t)(b * NCHUNK + c) * NH + h) * HD * DSTATE;
#pragma unroll
    for (int i = 0; i < 4; i++)
#pragma unroll
        for (int j = 0; j < 8; j++)
            g_states[base + (ty * 4 + i) * DSTATE + tx * 8 + j] = acc[i][j];
}

// ---------------- K7: sequential chunk scan ----------------
__global__ void k_scan() {
    int h = blockIdx.x % NH, b = blockIdx.x / NH;
    int tid = threadIdx.x;
    float s[32];
#pragma unroll
    for (int k = 0; k < 32; k++) s[k] = 0.f;
    for (int c = 0; c < NCHUNK; c++) {
        float cd = expf(g_Acs[(b * NH + h) * SEQL + c * CH + 127]);
        size_t base = ((size_t)(b * NCHUNK + c) * NH + h) * HD * DSTATE;
#pragma unroll
        for (int k = 0; k < 32; k++) {
            int e = k * 256 + tid;
            g_prev[base + e] = s[k];
            s[k] = s[k] * cd + g_states[base + e];
        }
    }
}

// ---------------- K8: S = C @ B^T ----------------
__global__ void __launch_bounds__(256) k_cb() {
    int c = blockIdx.x % NCHUNK, b = blockIdx.x / NCHUNK;
    __shared__ float sC[32][132];
    __shared__ float sBm[32][132];
    int tid = threadIdx.x, tx = tid & 15, ty = tid >> 4;
    float acc[8][8];
#pragma unroll
    for (int i = 0; i < 8; i++)
#pragma unroll
        for (int j = 0; j < 8; j++) acc[i][j] = 0.f;

    for (int k0 = 0; k0 < DSTATE; k0 += 32) {
        for (int i = tid; i < 32 * 128; i += 256) {
            int kk = i & 31, l = i >> 5;
            int row = b * SEQL + c * CH + l;
            sC[kk][l]  = g_xBC[(size_t)row * CONVCH + DIN + DSTATE + k0 + kk];
            sBm[kk][l] = g_xBC[(size_t)row * CONVCH + DIN + k0 + kk];
        }
        __syncthreads();
#pragma unroll
        for (int kk = 0; kk < 32; kk++) {
            float a[8], bv[8];
#pragma unroll
            for (int i = 0; i < 8; i++) a[i] = sC[kk][ty * 8 + i];
#pragma unroll
            for (int j = 0; j < 8; j++) bv[j] = sBm[kk][tx * 8 + j];
#pragma unroll
            for (int i = 0; i < 8; i++)
#pragma unroll
                for (int j = 0; j < 8; j++) acc[i][j] += a[i] * bv[j];
        }
        __syncthreads();
    }
    size_t base = (size_t)(b * NCHUNK + c) * CH * CH;
#pragma unroll
    for (int i = 0; i < 8; i++)
#pragma unroll
        for (int j = 0; j < 8; j++)
            g_S[base + (ty * 8 + i) * CH + tx * 8 + j] = acc[i][j];
}

// ---------------- K9: Y = Y_diag + Y_off + xs*D ----------------
__global__ void __launch_bounds__(256) k_y(const float* __restrict__ Dvec) {
    int h = blockIdx.x % NH;
    int c = (blockIdx.x / NH) % NCHUNK;
    int b = blockIdx.x / (NH * NCHUNK);
    __shared__ float sG[128][33];
    __shared__ float sT[32][69];
    __shared__ float sAcs[128];
    int tid = threadIdx.x;
    int pb = tid & 15;
    int lb = tid >> 4;
    if (tid < 128) sAcs[tid] = g_Acs[(b * NH + h) * SEQL + c * CH + tid];
    __syncthreads();

    float acc[8][4], acc2[8][4];
#pragma unroll
    for (int i = 0; i < 8; i++)
#pragma unroll
        for (int j = 0; j < 4; j++) { acc[i][j] = 0.f; acc2[i][j] = 0.f; }

    size_t Sbase = (size_t)(b * NCHUNK + c) * CH * CH;
    for (int st = 0; st < 4; st++) {
        for (int i = tid; i < 128 * 32; i += 256) {
            int s = i & 31, l = i >> 5;
            int sg = st * 32 + s;
            float v = 0.f;
            if (sg <= l) v = g_S[Sbase + l * CH + sg] * expf(sAcs[l] - sAcs[sg]);
            sG[l][s] = v;
        }
        for (int i = tid; i < 32 * 64; i += 256) {
            int p = i & 63, s = i >> 6;
            int row = b * SEQL + c * CH + st * 32 + s;
            sT[s][p] = g_xBC[(size_t)row * CONVCH + h * HD + p] * g_dt[row * NH + h];
        }
        __syncthreads();
#pragma unroll
        for (int s = 0; s < 32; s++) {
            float gv[8], xv[4];
#pragma unroll
            for (int i = 0; i < 8; i++) gv[i] = sG[lb * 8 + i][s];
#pragma unroll
            for (int j = 0; j < 4; j++) xv[j] = sT[s][pb * 4 + j];
#pragma unroll
            for (int i = 0; i < 8; i++)
#pragma unroll
                for (int j = 0; j < 4; j++) acc[i][j] += gv[i] * xv[j];
        }
        __syncthreads();
    }
    size_t Pbase = ((size_t)(b * NCHUNK + c) * NH + h) * HD * DSTATE;
    for (int nt = 0; nt < 4; nt++) {
        for (int i = tid; i < 128 * 32; i += 256) {
            int n = i & 31, l = i >> 5;
            int row = b * SEQL + c * CH + l;
            sG[l][n] = g_xBC[(size_t)row * CONVCH + DIN + DSTATE + nt * 32 + n];
        }
        for (int i = tid; i < 32 * 64; i += 256) {
            int n = i & 31, p = i >> 5;
            sT[n][p] = g_prev[Pbase + p * DSTATE + nt * 32 + n];
        }
        __syncthreads();
#pragma unroll
        for (int n = 0; n < 32; n++) {
            float gv[8], pv[4];
#pragma unroll
            for (int i = 0; i < 8; i++) gv[i] = sG[lb * 8 + i][n];
#pragma unroll
            for (int j = 0; j < 4; j++) pv[j] = sT[n][pb * 4 + j];
#pragma unroll
            for (int i = 0; i < 8; i++)
#pragma unroll
                for (int j = 0; j < 4; j++) acc2[i][j] += gv[i] * pv[j];
        }
        __syncthreads();
    }
    float Dh = Dvec[h];
#pragma unroll
    for (int i = 0; i < 8; i++) {
        int l = lb * 8 + i;
        int row = b * SEQL + c * CH + l;
        float el = expf(sAcs[l]);
#pragma unroll
        for (int j = 0; j < 4; j++) {
            int p = pb * 4 + j;
            float xsv = g_xBC[(size_t)row * CONVCH + h * HD + p];
            g_y[(size_t)row * DIN + h * HD + p] = acc[i][j] + el * acc2[i][j] + xsv * Dh;
        }
    }
}

// ---------------- K10: gated rmsnorm ----------------
__global__ void k_gnorm(const float* __restrict__ gnorm_w) {
    int row = blockIdx.x;
    __shared__ float st[DIN];
    __shared__ float sred[8];
    float ss = 0.f;
    for (int i = threadIdx.x; i < DIN; i += 256) {
        float z = g_zx[(size_t)row * DPROJ + i];
        float t = g_y[(size_t)row * DIN + i] * (z / (1.f + expf(-z)));
        st[i] = t;
        ss += t * t;
    }
    for (int o = 16; o > 0; o >>= 1) ss += __shfl_xor_sync(0xffffffffu, ss, o);
    if ((threadIdx.x & 31) == 0) sred[threadIdx.x >> 5] = ss;
    __syncthreads();
    if (threadIdx.x == 0) {
        float t = 0.f;
        for (int i = 0; i < 8; i++) t += sred[i];
        sred[0] = t;
    }
    __syncthreads();
    float scale = rsqrtf(sred[0] / (float)DIN + EPSV);
    for (int i = threadIdx.x; i < DIN; i += 256)
        g_y[(size_t)row * DIN + i] = st[i] * scale * gnorm_w[i];
}

// ---------------- host-side helpers ----------------
static void cvt(const float* src, __nv_bfloat16* hi, __nv_bfloat16* lo,
                long nvalid, long total) {
    long blocks = (total / 8 + 255) / 256;
    k_cvt<<<(unsigned)blocks, 256>>>(src, hi, lo, nvalid, total);
}

static void hgemm(const __nv_bfloat16* Ahi, const __nv_bfloat16* Alo, int K, int flipA,
                  const __nv_bfloat16* Whi, const __nv_bfloat16* Wlo, int Ntot,
                  float* C, int ldc, int flipC,
                  const float* resid, const float* bias) {
    cudaFuncSetAttribute(k_hgemm, cudaFuncAttributeMaxDynamicSharedMemorySize, HSMEM);
    dim3 grid((Ntot + 127) / 128, ROWS / 128);
    k_hgemm<<<grid, 256, HSMEM>>>(Ahi, Alo, K, flipA, Whi, Wlo, Ntot, C, ldc, flipC,
                                  resid, bias);
}

extern "C" void kernel_launch(void* const* d_in, const int* in_sizes, int n_in,
                              void* d_out, int out_size) {
    (void)in_sizes; (void)n_in; (void)out_size;
    const float* x         = (const float*)d_in[0];
    const float* norm_w    = (const float*)d_in[1];
    const float* out_w_blk = (const float*)d_in[2];
    const float* out_b_blk = (const float*)d_in[3];

    float *p_xn, *p_zx, *p_y, *p_ycat;
    __nv_bfloat16 *p_XNhi, *p_XNlo, *p_Ahi, *p_Alo, *p_Whi, *p_Wlo;
    cudaGetSymbolAddress((void**)&p_xn,   g_xn);
    cudaGetSymbolAddress((void**)&p_zx,   g_zx);
    cudaGetSymbolAddress((void**)&p_y,    g_y);
    cudaGetSymbolAddress((void**)&p_ycat, g_ycat);
    cudaGetSymbolAddress((void**)&p_XNhi, g_XNhi);
    cudaGetSymbolAddress((void**)&p_XNlo, g_XNlo);
    cudaGetSymbolAddress((void**)&p_Ahi,  g_Ahi);
    cudaGetSymbolAddress((void**)&p_Alo,  g_Alo);
    cudaGetSymbolAddress((void**)&p_Whi,  g_Whi);
    cudaGetSymbolAddress((void**)&p_Wlo,  g_Wlo);

    k_rmsnorm<<<ROWS, 256>>>(x, norm_w);
    cvt(p_xn, p_XNhi, p_XNlo, (long)ROWS * DM, (long)ROWS * DM);

    for (int d = 0; d < 2; d++) {
        const float* in_w    = (const float*)d_in[4 + d * 8 + 0];
        const float* conv_w  = (const float*)d_in[4 + d * 8 + 1];
        const float* conv_b  = (const float*)d_in[4 + d * 8 + 2];
        const float* dt_bias = (const float*)d_in[4 + d * 8 + 3];
        const float* A_log   = (const float*)d_in[4 + d * 8 + 4];
        const float* Dv      = (const float*)d_in[4 + d * 8 + 5];
        const float* gnw     = (const float*)d_in[4 + d * 8 + 6];
        const float* out_w   = (const float*)d_in[4 + d * 8 + 7];

        // in-proj: zx = xn @ in_w^T  (A flipped for backward dir)
        cvt(in_w, p_Whi, p_Wlo, (long)DPROJ * DM, (long)NPADW * DM);
        hgemm(p_XNhi, p_XNlo, DM, d, p_Whi, p_Wlo, DPROJ, p_zx, DPROJ, 0,
              nullptr, nullptr);

        k_dt<<<(ROWS * NH + 255) / 256, 256>>>(dt_bias);
        k_conv<<<(ROWS * CONVCH + 255) / 256, 256>>>(conv_w, conv_b);
        k_acs<<<BATCH * NH * NCHUNK, 128>>>(A_log);
        k_states<<<BATCH * NCHUNK * NH, 256>>>();
        k_scan<<<BATCH * NH, 256>>>();
        k_cb<<<BATCH * NCHUNK, 256>>>();
        k_y<<<BATCH * NCHUNK * NH, 256>>>(Dv);
        k_gnorm<<<ROWS, 256>>>(gnw);

        // out-proj: ycat[:, d*DM:] = y @ out_w^T  (C flipped for backward dir)
        cvt(p_y, p_Ahi, p_Alo, (long)ROWS * DIN, (long)ROWS * DIN);
        cvt(out_w, p_Whi, p_Wlo, (long)DM * DIN, (long)DM * DIN);
        hgemm(p_Ahi, p_Alo, DIN, 0, p_Whi, p_Wlo, DM, p_ycat + d * DM, 2 * DM, d,
              nullptr, nullptr);
    }

    // final: out = x + ycat @ out_w_blk^T + bias
    cvt(p_ycat, p_Ahi, p_Alo, (long)ROWS * 2 * DM, (long)ROWS * 2 * DM);
    cvt(out_w_blk, p_Whi, p_Wlo, (long)DM * 2 * DM, (long)DM * 2 * DM);
    hgemm(p_Ahi, p_Alo, 2 * DM, 0, p_Whi, p_Wlo, DM, (float*)d_out, DM, 0,
          x, out_b_blk);
}

// round 5
// speedup vs baseline: 3.8142x; 1.1690x over previous
#include <cuda_runtime.h>
#include <cuda_bf16.h>
#include <math.h>
#include <stdint.h>

// ---------------- problem constants ----------------
#define BATCH   2
#define SEQL    2048
#define DM      1024
#define DIN     2048      // D_INNER
#define DSTATE  128
#define NH      32
#define HD      64
#define DPROJ   4384      // D_IN_PROJ
#define CONVCH  2304      // D_INNER + 2*D_STATE
#define NCHUNK  16
#define CH      128
#define EPSV    1e-5f
#define ROWS    (BATCH*SEQL)   // 4096
#define NPADW   4480           // 35*128, padded N for widest weight

// ---------------- scratch (device globals; [2] = per direction) ----------------
__device__ float g_xn    [ROWS*DM];
__device__ float g_zx    [2][ROWS*DPROJ];
__device__ float g_xBC   [2][ROWS*CONVCH];
__device__ float g_dt    [2][ROWS*NH];
__device__ float g_Acs   [2][BATCH*NH*SEQL];
__device__ float g_states[2][BATCH*NCHUNK*NH*HD*DSTATE];
__device__ float g_prev  [2][BATCH*NCHUNK*NH*HD*DSTATE];
__device__ float g_S     [2][BATCH*NCHUNK*CH*CH];
__device__ float g_y     [2][ROWS*DIN];
__device__ float g_ycat  [ROWS*2*DM];

__device__ __nv_bfloat16 g_XNhi[ROWS*DM];
__device__ __nv_bfloat16 g_XNlo[ROWS*DM];
__device__ __nv_bfloat16 g_Ahi [2][ROWS*DIN];   // [0] reused for ycat at the end
__device__ __nv_bfloat16 g_Alo [2][ROWS*DIN];
__device__ __nv_bfloat16 g_Whi [2][NPADW*DM];
__device__ __nv_bfloat16 g_Wlo [2][NPADW*DM];

// ---------------- asm helpers ----------------
__device__ __forceinline__ uint32_t smem_u32(const void* p) {
    uint32_t a;
    asm("{ .reg .u64 t; cvta.to.shared.u64 t, %1; cvt.u32.u64 %0, t; }" : "=r"(a) : "l"(p));
    return a;
}
#define CP16(d, s) asm volatile("cp.async.cg.shared.global [%0], [%1], 16;" :: "r"(d), "l"(s))
#define CP_COMMIT() asm volatile("cp.async.commit_group;")
#define LDSM4(r, a) asm volatile("ldmatrix.sync.aligned.m8n8.x4.shared.b16 {%0,%1,%2,%3}, [%4];" \
    : "=r"((r)[0]), "=r"((r)[1]), "=r"((r)[2]), "=r"((r)[3]) : "r"(a))
#define MMA16816(d, a, b) asm volatile( \
    "mma.sync.aligned.m16n8k16.row.col.f32.bf16.bf16.f32 " \
    "{%0,%1,%2,%3}, {%4,%5,%6,%7}, {%8,%9}, {%0,%1,%2,%3};" \
    : "+f"((d)[0]), "+f"((d)[1]), "+f"((d)[2]), "+f"((d)[3]) \
    : "r"((a)[0]), "r"((a)[1]), "r"((a)[2]), "r"((a)[3]), "r"((b)[0]), "r"((b)[1]))

__device__ __forceinline__ uint32_t sw_addr(uint32_t base, int row, int chunk) {
    return base + (uint32_t)row * 64u + ((((uint32_t)chunk) ^ (((uint32_t)row >> 1) & 3u)) << 4);
}

// ---------------- fp32 -> bf16 hi/lo conversion (with zero padding) ----------------
__global__ void k_cvt(const float* __restrict__ src, __nv_bfloat16* __restrict__ hi,
                      __nv_bfloat16* __restrict__ lo, long nvalid, long total) {
    long idx = ((long)blockIdx.x * 256 + threadIdx.x) * 8;
    if (idx >= total) return;
    uint4 hq = make_uint4(0, 0, 0, 0), lq = make_uint4(0, 0, 0, 0);
    if (idx < nvalid) {
        float4 f0 = *reinterpret_cast<const float4*>(src + idx);
        float4 f1 = *reinterpret_cast<const float4*>(src + idx + 4);
        float f[8] = {f0.x, f0.y, f0.z, f0.w, f1.x, f1.y, f1.z, f1.w};
        uint32_t h[8], l[8];
#pragma unroll
        for (int i = 0; i < 8; i++) {
            __nv_bfloat16 hb = __float2bfloat16(f[i]);
            float rr = f[i] - __bfloat162float(hb);
            __nv_bfloat16 lb = __float2bfloat16(rr);
            h[i] = __bfloat16_as_ushort(hb);
            l[i] = __bfloat16_as_ushort(lb);
        }
        hq.x = (h[1] << 16) | h[0]; hq.y = (h[3] << 16) | h[2];
        hq.z = (h[5] << 16) | h[4]; hq.w = (h[7] << 16) | h[6];
        lq.x = (l[1] << 16) | l[0]; lq.y = (l[3] << 16) | l[2];
        lq.z = (l[5] << 16) | l[4]; lq.w = (l[7] << 16) | l[6];
    }
    *reinterpret_cast<uint4*>(hi + idx) = hq;
    *reinterpret_cast<uint4*>(lo + idx) = lq;
}

// ---------------- HMMA GEMM: C[4096,N] = A[4096,K] @ W[N,K]^T (+bias +resid) ----------------
#define HSMEM 65536   // 2 stages x 32KB

__global__ void __launch_bounds__(256, 2) k_hgemm(
    const __nv_bfloat16* __restrict__ Ahi, const __nv_bfloat16* __restrict__ Alo,
    int K, int flipA,
    const __nv_bfloat16* __restrict__ Whi, const __nv_bfloat16* __restrict__ Wlo,
    int Ntot, float* __restrict__ C, int ldc, int flipC,
    const float* __restrict__ resid, const float* __restrict__ bias)
{
    extern __shared__ char smraw[];
    const uint32_t sb = smem_u32(smraw);
    const int tid = threadIdx.x, lane = tid & 31, wid = tid >> 5;
    const int bm = blockIdx.y * 128, bn = blockIdx.x * 128;
    const int wm = (wid & 1) * 64, wn = (wid >> 1) * 32;

    float acc[4][4][4];
#pragma unroll
    for (int i = 0; i < 4; i++)
#pragma unroll
        for (int j = 0; j < 4; j++)
#pragma unroll
            for (int k = 0; k < 4; k++) acc[i][j][k] = 0.f;

    const int ktiles = K / 32;

    auto load_stage = [&](int s, int k0) {
        uint32_t base = sb + s * 32768;
#pragma unroll
        for (int it = 0; it < 2; it++) {
            int q = tid + it * 256;
            int r = q >> 2, c = q & 3;
            int gr = bm + r, pr = gr;
            if (flipA) pr = (gr & ~(SEQL - 1)) + (SEQL - 1 - (gr & (SEQL - 1)));
            uint32_t d = sw_addr(base, r, c);
            size_t aoff = (size_t)pr * K + k0 + c * 8;
            CP16(d,         (const char*)(Ahi + aoff));
            CP16(d + 8192,  (const char*)(Alo + aoff));
            size_t woff = (size_t)(bn + r) * K + k0 + c * 8;
            CP16(d + 16384, (const char*)(Whi + woff));
            CP16(d + 24576, (const char*)(Wlo + woff));
        }
        CP_COMMIT();
    };

    load_stage(0, 0);

    for (int i = 0; i < ktiles; i++) {
        if (i + 1 < ktiles) {
            load_stage((i + 1) & 1, (i + 1) * 32);
            asm volatile("cp.async.wait_group 1;");
        } else {
            asm volatile("cp.async.wait_group 0;");
        }
        __syncthreads();
        uint32_t base = sb + (i & 1) * 32768;
#pragma unroll
        for (int ks = 0; ks < 2; ks++) {
            const int kb = ks * 2;
            uint32_t bh[4][2], bl[4][2];
#pragma unroll
            for (int p2 = 0; p2 < 2; p2++) {
                int rr = wn + p2 * 16 + ((lane >> 4) << 3) + (lane & 7);
                int cc = kb + ((lane >> 3) & 1);
                uint32_t bd = sw_addr(base + 16384, rr, cc);
                uint32_t t[4];
                LDSM4(t, bd);
                bh[p2 * 2][0] = t[0]; bh[p2 * 2][1] = t[1];
                bh[p2 * 2 + 1][0] = t[2]; bh[p2 * 2 + 1][1] = t[3];
                LDSM4(t, bd + 8192);
                bl[p2 * 2][0] = t[0]; bl[p2 * 2][1] = t[1];
                bl[p2 * 2 + 1][0] = t[2]; bl[p2 * 2 + 1][1] = t[3];
            }
            int arow = (lane & 15);
            int acol = kb + (lane >> 4);
#pragma unroll
            for (int mf = 0; mf < 4; mf++) {
                uint32_t a[4];
                LDSM4(a, sw_addr(base, wm + mf * 16 + arow, acol));
#pragma unroll
                for (int nf = 0; nf < 4; nf++) MMA16816(acc[mf][nf], a, bh[nf]);
#pragma unroll
                for (int nf = 0; nf < 4; nf++) MMA16816(acc[mf][nf], a, bl[nf]);
                LDSM4(a, sw_addr(base + 8192, wm + mf * 16 + arow, acol));
#pragma unroll
                for (int nf = 0; nf < 4; nf++) MMA16816(acc[mf][nf], a, bh[nf]);
            }
        }
        __syncthreads();
    }

    // epilogue
#pragma unroll
    for (int mf = 0; mf < 4; mf++) {
        int r0 = bm + wm + mf * 16 + (lane >> 2);
        int r1 = r0 + 8;
        int p0 = r0, p1 = r1;
        if (flipC) {
            p0 = (r0 & ~(SEQL - 1)) + (SEQL - 1 - (r0 & (SEQL - 1)));
            p1 = (r1 & ~(SEQL - 1)) + (SEQL - 1 - (r1 & (SEQL - 1)));
        }
#pragma unroll
        for (int nf = 0; nf < 4; nf++) {
            int col = bn + wn + nf * 8 + (lane & 3) * 2;
            if (col >= Ntot) continue;
            float2 v0 = make_float2(acc[mf][nf][0], acc[mf][nf][1]);
            float2 v1 = make_float2(acc[mf][nf][2], acc[mf][nf][3]);
            if (bias) {
                float b0 = bias[col], b1 = bias[col + 1];
                v0.x += b0; v0.y += b1; v1.x += b0; v1.y += b1;
            }
            if (resid) {
                float2 q0 = *reinterpret_cast<const float2*>(resid + (size_t)p0 * ldc + col);
                float2 q1 = *reinterpret_cast<const float2*>(resid + (size_t)p1 * ldc + col);
                v0.x += q0.x; v0.y += q0.y; v1.x += q1.x; v1.y += q1.y;
            }
            *reinterpret_cast<float2*>(C + (size_t)p0 * ldc + col) = v0;
            *reinterpret_cast<float2*>(C + (size_t)p1 * ldc + col) = v1;
        }
    }
}

// ---------------- K1: rmsnorm over d_model ----------------
__global__ void k_rmsnorm(const float* __restrict__ x, const float* __restrict__ w) {
    int row = blockIdx.x;
    const float* xr = x + (size_t)row * DM;
    float ss = 0.f;
    for (int i = threadIdx.x; i < DM; i += 256) { float v = xr[i]; ss += v * v; }
    __shared__ float sred[8];
    for (int o = 16; o > 0; o >>= 1) ss += __shfl_xor_sync(0xffffffffu, ss, o);
    if ((threadIdx.x & 31) == 0) sred[threadIdx.x >> 5] = ss;
    __syncthreads();
    if (threadIdx.x == 0) {
        float t = 0.f;
        for (int i = 0; i < 8; i++) t += sred[i];
        sred[0] = t;
    }
    __syncthreads();
    float scale = rsqrtf(sred[0] / (float)DM + EPSV);
    for (int i = threadIdx.x; i < DM; i += 256)
        g_xn[(size_t)row * DM + i] = xr[i] * scale * w[i];
}

// ---------------- conv (4 channels / thread) + bias + silu ----------------
__global__ void k_conv(const float* __restrict__ zx, float* __restrict__ xBC,
                       const float* __restrict__ conv_w, const float* __restrict__ conv_b) {
    int idx = blockIdx.x * 256 + threadIdx.x;
    if (idx >= ROWS * (CONVCH / 4)) return;
    int c4 = idx % (CONVCH / 4);
    int r  = idx / (CONVCH / 4);
    int ch = c4 * 4;
    int l = r & (SEQL - 1);
    float a0 = conv_b[ch], a1 = conv_b[ch+1], a2 = conv_b[ch+2], a3 = conv_b[ch+3];
#pragma unroll
    for (int k = 0; k < 4; k++) {
        int ll = l - 3 + k;
        if (ll >= 0) {
            float4 v = *reinterpret_cast<const float4*>(zx + (size_t)(r - 3 + k) * DPROJ + DIN + ch);
            a0 += v.x * conv_w[(ch+0)*4 + k];
            a1 += v.y * conv_w[(ch+1)*4 + k];
            a2 += v.z * conv_w[(ch+2)*4 + k];
            a3 += v.w * conv_w[(ch+3)*4 + k];
        }
    }
    float4 o;
    o.x = a0 / (1.f + expf(-a0)); o.y = a1 / (1.f + expf(-a1));
    o.z = a2 / (1.f + expf(-a2)); o.w = a3 / (1.f + expf(-a3));
    *reinterpret_cast<float4*>(xBC + (size_t)r * CONVCH + ch) = o;
}

// ---------------- fused dt(softplus) + per-chunk cumsum ----------------
__global__ void k_acs(const float* __restrict__ zx, const float* __restrict__ dt_bias,
                      const float* __restrict__ A_log,
                      float* __restrict__ dt, float* __restrict__ Acs) {
    int c = blockIdx.x % NCHUNK;
    int h = (blockIdx.x / NCHUNK) % NH;
    int b = blockIdx.x / (NCHUNK * NH);
    int l = threadIdx.x;
    int row = b * SEQL + c * CH + l;
    float v = zx[(size_t)row * DPROJ + DIN + CONVCH + h] + dt_bias[h];
    float dtv = (v > 20.f) ? v : log1pf(expf(v));
    dt[row * NH + h] = dtv;
    float Aneg = -expf(A_log[h]);
    float x = Aneg * dtv;
    __shared__ float wsum[4];
    for (int o = 1; o < 32; o <<= 1) {
        float t = __shfl_up_sync(0xffffffffu, x, o);
        if ((l & 31) >= o) x += t;
    }
    if ((l & 31) == 31) wsum[l >> 5] = x;
    __syncthreads();
    float add = 0.f;
    int w = l >> 5;
    for (int i = 0; i < w; i++) add += wsum[i];
    Acs[(b * NH + h) * SEQL + c * CH + l] = x + add;
}

// ---------------- chunk states ----------------
__global__ void __launch_bounds__(256) k_states(
    const float* __restrict__ xBC, const float* __restrict__ dt,
    const float* __restrict__ Acs, float* __restrict__ states) {
    int h = blockIdx.x % NH;
    int c = (blockIdx.x / NH) % NCHUNK;
    int b = blockIdx.x / (NH * NCHUNK);
    __shared__ float sX[32][64];
    __shared__ float sB[32][132];
    int tid = threadIdx.x;
    int tx = tid & 15, ty = tid >> 4;
    float acc[4][8];
#pragma unroll
    for (int i = 0; i < 4; i++)
#pragma unroll
        for (int j = 0; j < 8; j++) acc[i][j] = 0.f;

    const float* AcsRow = Acs + (b * NH + h) * SEQL + c * CH;
    float AcsLast = AcsRow[127];

    for (int lt = 0; lt < 4; lt++) {
        for (int i = tid; i < 32 * 64; i += 256) {
            int l = i >> 6, p = i & 63;
            int row = b * SEQL + c * CH + lt * 32 + l;
            float w = dt[row * NH + h] * expf(AcsLast - AcsRow[lt * 32 + l]);
            sX[l][p] = xBC[(size_t)row * CONVCH + h * HD + p] * w;
        }
        for (int i = tid; i < 32 * 128; i += 256) {
            int l = i >> 7, n = i & 127;
            int row = b * SEQL + c * CH + lt * 32 + l;
            sB[l][n] = xBC[(size_t)row * CONVCH + DIN + n];
        }
        __syncthreads();
#pragma unroll
        for (int l = 0; l < 32; l++) {
            float xv[4], bv[8];
#pragma unroll
            for (int i = 0; i < 4; i++) xv[i] = sX[l][ty * 4 + i];
#pragma unroll
            for (int j = 0; j < 8; j++) bv[j] = sB[l][tx * 8 + j];
#pragma unroll
            for (int i = 0; i < 4; i++)
#pragma unroll
                for (int j = 0; j < 8; j++) acc[i][j] += xv[i] * bv[j];
        }
        __syncthreads();
    }
    size_t base = ((size_t)(b * NCHUNK + c) * NH + h) * HD * DSTATE;
#pragma unroll
    for (int i = 0; i < 4; i++)
#pragma unroll
        for (int j = 0; j < 8; j++)
            states[base + (ty * 4 + i) * DSTATE + tx * 8 + j] = acc[i][j];
}

// ---------------- sequential chunk scan ----------------
__global__ void k_scan(const float* __restrict__ Acs, const float* __restrict__ states,
                       float* __restrict__ prev) {
    int h = blockIdx.x % NH, b = blockIdx.x / NH;
    int tid = threadIdx.x;
    float s[32];
#pragma unroll
    for (int k = 0; k < 32; k++) s[k] = 0.f;
    for (int c = 0; c < NCHUNK; c++) {
        float cd = expf(Acs[(b * NH + h) * SEQL + c * CH + 127]);
        size_t base = ((size_t)(b * NCHUNK + c) * NH + h) * HD * DSTATE;
#pragma unroll
        for (int k = 0; k < 32; k++) {
            int e = k * 256 + tid;
            prev[base + e] = s[k];
            s[k] = s[k] * cd + states[base + e];
        }
    }
}

// ---------------- S = C @ B^T ----------------
__global__ void __launch_bounds__(256) k_cb(const float* __restrict__ xBC,
                                            float* __restrict__ S) {
    int c = blockIdx.x % NCHUNK, b = blockIdx.x / NCHUNK;
    __shared__ float sC[32][132];
    __shared__ float sBm[32][132];
    int tid = threadIdx.x, tx = tid & 15, ty = tid >> 4;
    float acc[8][8];
#pragma unroll
    for (int i = 0; i < 8; i++)
#pragma unroll
        for (int j = 0; j < 8; j++) acc[i][j] = 0.f;

    for (int k0 = 0; k0 < DSTATE; k0 += 32) {
        for (int i = tid; i < 32 * 128; i += 256) {
            int kk = i & 31, l = i >> 5;
            int row = b * SEQL + c * CH + l;
            sC[kk][l]  = xBC[(size_t)row * CONVCH + DIN + DSTATE + k0 + kk];
            sBm[kk][l] = xBC[(size_t)row * CONVCH + DIN + k0 + kk];
        }
        __syncthreads();
#pragma unroll
        for (int kk = 0; kk < 32; kk++) {
            float a[8], bv[8];
#pragma unroll
            for (int i = 0; i < 8; i++) a[i] = sC[kk][ty * 8 + i];
#pragma unroll
            for (int j = 0; j < 8; j++) bv[j] = sBm[kk][tx * 8 + j];
#pragma unroll
            for (int i = 0; i < 8; i++)
#pragma unroll
                for (int j = 0; j < 8; j++) acc[i][j] += a[i] * bv[j];
        }
        __syncthreads();
    }
    size_t base = (size_t)(b * NCHUNK + c) * CH * CH;
#pragma unroll
    for (int i = 0; i < 8; i++)
#pragma unroll
        for (int j = 0; j < 8; j++)
            S[base + (ty * 8 + i) * CH + tx * 8 + j] = acc[i][j];
}

// ---------------- Y = Y_diag + Y_off + xs*D ----------------
__global__ void __launch_bounds__(256) k_y(
    const float* __restrict__ xBC, const float* __restrict__ dt,
    const float* __restrict__ Acs, const float* __restrict__ prev,
    const float* __restrict__ S, float* __restrict__ y,
    const float* __restrict__ Dvec) {
    int h = blockIdx.x % NH;
    int c = (blockIdx.x / NH) % NCHUNK;
    int b = blockIdx.x / (NH * NCHUNK);
    __shared__ float sG[128][33];
    __shared__ float sT[32][69];
    __shared__ float sAcs[128];
    int tid = threadIdx.x;
    int pb = tid & 15;
    int lb = tid >> 4;
    if (tid < 128) sAcs[tid] = Acs[(b * NH + h) * SEQL + c * CH + tid];
    __syncthreads();

    float acc[8][4], acc2[8][4];
#pragma unroll
    for (int i = 0; i < 8; i++)
#pragma unroll
        for (int j = 0; j < 4; j++) { acc[i][j] = 0.f; acc2[i][j] = 0.f; }

    size_t Sbase = (size_t)(b * NCHUNK + c) * CH * CH;
    for (int st = 0; st < 4; st++) {
        for (int i = tid; i < 128 * 32; i += 256) {
            int s = i & 31, l = i >> 5;
            int sg = st * 32 + s;
            float v = 0.f;
            if (sg <= l) v = S[Sbase + l * CH + sg] * expf(sAcs[l] - sAcs[sg]);
            sG[l][s] = v;
        }
        for (int i = tid; i < 32 * 64; i += 256) {
            int p = i & 63, s = i >> 6;
            int row = b * SEQL + c * CH + st * 32 + s;
            sT[s][p] = xBC[(size_t)row * CONVCH + h * HD + p] * dt[row * NH + h];
        }
        __syncthreads();
#pragma unroll
        for (int s = 0; s < 32; s++) {
            float gv[8], xv[4];
#pragma unroll
            for (int i = 0; i < 8; i++) gv[i] = sG[lb * 8 + i][s];
#pragma unroll
            for (int j = 0; j < 4; j++) xv[j] = sT[s][pb * 4 + j];
#pragma unroll
            for (int i = 0; i < 8; i++)
#pragma unroll
                for (int j = 0; j < 4; j++) acc[i][j] += gv[i] * xv[j];
        }
        __syncthreads();
    }
    size_t Pbase = ((size_t)(b * NCHUNK + c) * NH + h) * HD * DSTATE;
    for (int nt = 0; nt < 4; nt++) {
        for (int i = tid; i < 128 * 32; i += 256) {
            int n = i & 31, l = i >> 5;
            int row = b * SEQL + c * CH + l;
            sG[l][n] = xBC[(size_t)row * CONVCH + DIN + DSTATE + nt * 32 + n];
        }
        for (int i = tid; i < 32 * 64; i += 256) {
            int n = i & 31, p = i >> 5;
            sT[n][p] = prev[Pbase + p * DSTATE + nt * 32 + n];
        }
        __syncthreads();
#pragma unroll
        for (int n = 0; n < 32; n++) {
            float gv[8], pv[4];
#pragma unroll
            for (int i = 0; i < 8; i++) gv[i] = sG[lb * 8 + i][n];
#pragma unroll
            for (int j = 0; j < 4; j++) pv[j] = sT[n][pb * 4 + j];
#pragma unroll
            for (int i = 0; i < 8; i++)
#pragma unroll
                for (int j = 0; j < 4; j++) acc2[i][j] += gv[i] * pv[j];
        }
        __syncthreads();
    }
    float Dh = Dvec[h];
#pragma unroll
    for (int i = 0; i < 8; i++) {
        int l = lb * 8 + i;
        int row = b * SEQL + c * CH + l;
        float el = expf(sAcs[l]);
#pragma unroll
        for (int j = 0; j < 4; j++) {
            int p = pb * 4 + j;
            float xsv = xBC[(size_t)row * CONVCH + h * HD + p];
            y[(size_t)row * DIN + h * HD + p] = acc[i][j] + el * acc2[i][j] + xsv * Dh;
        }
    }
}

// ---------------- gated rmsnorm ----------------
__global__ void k_gnorm(const float* __restrict__ zx, float* __restrict__ y,
                        const float* __restrict__ gnorm_w) {
    int row = blockIdx.x;
    __shared__ float st[DIN];
    __shared__ float sred[8];
    float ss = 0.f;
    for (int i = threadIdx.x; i < DIN; i += 256) {
        float z = zx[(size_t)row * DPROJ + i];
        float t = y[(size_t)row * DIN + i] * (z / (1.f + expf(-z)));
        st[i] = t;
        ss += t * t;
    }
    for (int o = 16; o > 0; o >>= 1) ss += __shfl_xor_sync(0xffffffffu, ss, o);
    if ((threadIdx.x & 31) == 0) sred[threadIdx.x >> 5] = ss;
    __syncthreads();
    if (threadIdx.x == 0) {
        float t = 0.f;
        for (int i = 0; i < 8; i++) t += sred[i];
        sred[0] = t;
    }
    __syncthreads();
    float scale = rsqrtf(sred[0] / (float)DIN + EPSV);
    for (int i = threadIdx.x; i < DIN; i += 256)
        y[(size_t)row * DIN + i] = st[i] * scale * gnorm_w[i];
}

// ---------------- host helpers ----------------
static void cvt(cudaStream_t st, const float* src, __nv_bfloat16* hi, __nv_bfloat16* lo,
                long nvalid, long total) {
    long blocks = (total / 8 + 255) / 256;
    k_cvt<<<(unsigned)blocks, 256, 0, st>>>(src, hi, lo, nvalid, total);
}

static void hgemm(cudaStream_t st,
                  const __nv_bfloat16* Ahi, const __nv_bfloat16* Alo, int K, int flipA,
                  const __nv_bfloat16* Whi, const __nv_bfloat16* Wlo, int Ntot,
                  float* C, int ldc, int flipC,
                  const float* resid, const float* bias) {
    dim3 grid((Ntot + 127) / 128, ROWS / 128);
    k_hgemm<<<grid, 256, HSMEM, st>>>(Ahi, Alo, K, flipA, Whi, Wlo, Ntot, C, ldc, flipC,
                                      resid, bias);
}

extern "C" void kernel_launch(void* const* d_in, const int* in_sizes, int n_in,
                              void* d_out, int out_size) {
    (void)in_sizes; (void)n_in; (void)out_size;
    const float* x         = (const float*)d_in[0];
    const float* norm_w    = (const float*)d_in[1];
    const float* out_w_blk = (const float*)d_in[2];
    const float* out_b_blk = (const float*)d_in[3];

    // infra objects (created once, pre-capture on the correctness call)
    static cudaStream_t s2 = nullptr;
    static cudaEvent_t evA = nullptr, evB = nullptr;
    static bool smem_set = false;
    if (!s2) {
        cudaStreamCreateWithFlags(&s2, cudaStreamNonBlocking);
        cudaEventCreateWithFlags(&evA, cudaEventDisableTiming);
        cudaEventCreateWithFlags(&evB, cudaEventDisableTiming);
    }
    if (!smem_set) {
        cudaFuncSetAttribute(k_hgemm, cudaFuncAttributeMaxDynamicSharedMemorySize, HSMEM);
        smem_set = true;
    }

    float *p_xn, *p_zx, *p_xBC, *p_dt, *p_Acs, *p_states, *p_prev, *p_S, *p_y, *p_ycat;
    __nv_bfloat16 *p_XNhi, *p_XNlo, *p_Ahi, *p_Alo, *p_Whi, *p_Wlo;
    cudaGetSymbolAddress((void**)&p_xn,     g_xn);
    cudaGetSymbolAddress((void**)&p_zx,     g_zx);
    cudaGetSymbolAddress((void**)&p_xBC,    g_xBC);
    cudaGetSymbolAddress((void**)&p_dt,     g_dt);
    cudaGetSymbolAddress((void**)&p_Acs,    g_Acs);
    cudaGetSymbolAddress((void**)&p_states, g_states);
    cudaGetSymbolAddress((void**)&p_prev,   g_prev);
    cudaGetSymbolAddress((void**)&p_S,      g_S);
    cudaGetSymbolAddress((void**)&p_y,      g_y);
    cudaGetSymbolAddress((void**)&p_ycat,   g_ycat);
    cudaGetSymbolAddress((void**)&p_XNhi,   g_XNhi);
    cudaGetSymbolAddress((void**)&p_XNlo,   g_XNlo);
    cudaGetSymbolAddress((void**)&p_Ahi,    g_Ahi);
    cudaGetSymbolAddress((void**)&p_Alo,    g_Alo);
    cudaGetSymbolAddress((void**)&p_Whi,    g_Whi);
    cudaGetSymbolAddress((void**)&p_Wlo,    g_Wlo);

    k_rmsnorm<<<ROWS, 256, 0, 0>>>(x, norm_w);
    cvt(0, p_xn, p_XNhi, p_XNlo, (long)ROWS * DM, (long)ROWS * DM);

    // fork: direction 1 runs on s2
    cudaEventRecord(evA, 0);
    cudaStreamWaitEvent(s2, evA, 0);

    for (int d = 0; d < 2; d++) {
        cudaStream_t st = (d == 0) ? (cudaStream_t)0 : s2;
        const float* in_w    = (const float*)d_in[4 + d * 8 + 0];
        const float* conv_w  = (const float*)d_in[4 + d * 8 + 1];
        const float* conv_b  = (const float*)d_in[4 + d * 8 + 2];
        const float* dt_bias = (const float*)d_in[4 + d * 8 + 3];
        const float* A_log   = (const float*)d_in[4 + d * 8 + 4];
        const float* Dv      = (const float*)d_in[4 + d * 8 + 5];
        const float* gnw     = (const float*)d_in[4 + d * 8 + 6];
        const float* out_w   = (const float*)d_in[4 + d * 8 + 7];

        float* zx     = p_zx     + (size_t)d * ROWS * DPROJ;
        float* xBC    = p_xBC    + (size_t)d * ROWS * CONVCH;
        float* dt     = p_dt     + (size_t)d * ROWS * NH;
        float* Acs    = p_Acs    + (size_t)d * BATCH * NH * SEQL;
        float* states = p_states + (size_t)d * BATCH * NCHUNK * NH * HD * DSTATE;
        float* prev   = p_prev   + (size_t)d * BATCH * NCHUNK * NH * HD * DSTATE;
        float* S      = p_S      + (size_t)d * BATCH * NCHUNK * CH * CH;
        float* y      = p_y      + (size_t)d * ROWS * DIN;
        __nv_bfloat16* Ahi = p_Ahi + (size_t)d * ROWS * DIN;
        __nv_bfloat16* Alo = p_Alo + (size_t)d * ROWS * DIN;
        __nv_bfloat16* Whi = p_Whi + (size_t)d * NPADW * DM;
        __nv_bfloat16* Wlo = p_Wlo + (size_t)d * NPADW * DM;

        cvt(st, in_w, Whi, Wlo, (long)DPROJ * DM, (long)NPADW * DM);
        hgemm(st, p_XNhi, p_XNlo, DM, d, Whi, Wlo, DPROJ, zx, DPROJ, 0, nullptr, nullptr);

        k_conv<<<(ROWS * (CONVCH / 4) + 255) / 256, 256, 0, st>>>(zx, xBC, conv_w, conv_b);
        k_acs<<<BATCH * NH * NCHUNK, 128, 0, st>>>(zx, dt_bias, A_log, dt, Acs);
        k_states<<<BATCH * NCHUNK * NH, 256, 0, st>>>(xBC, dt, Acs, states);
        k_scan<<<BATCH * NH, 256, 0, st>>>(Acs, states, prev);
        k_cb<<<BATCH * NCHUNK, 256, 0, st>>>(xBC, S);
        k_y<<<BATCH * NCHUNK * NH, 256, 0, st>>>(xBC, dt, Acs, prev, S, y, Dv);
        k_gnorm<<<ROWS, 256, 0, st>>>(zx, y, gnw);

        cvt(st, y, Ahi, Alo, (long)ROWS * DIN, (long)ROWS * DIN);
        cvt(st, out_w, Whi, Wlo, (long)DM * DIN, (long)DM * DIN);
        hgemm(st, Ahi, Alo, DIN, 0, Whi, Wlo, DM, p_ycat + d * DM, 2 * DM, d,
              nullptr, nullptr);
    }

    // join
    cudaEventRecord(evB, s2);
    cudaStreamWaitEvent(0, evB, 0);

    // final: out = x + ycat @ out_w_blk^T + bias   (reuse dir-0 staging)
    cvt(0, p_ycat, p_Ahi, p_Alo, (long)ROWS * 2 * DM, (long)ROWS * 2 * DM);
    cvt(0, out_w_blk, p_Whi, p_Wlo, (long)DM * 2 * DM, (long)DM * 2 * DM);
    hgemm(0, p_Ahi, p_Alo, 2 * DM, 0, p_Whi, p_Wlo, DM, (float*)d_out, DM, 0,
          x, out_b_blk);
}